// round 6
// baseline (speedup 1.0000x reference)
#include <cuda_runtime.h>
#include <math.h>

#define H 1024
#define V 50257
#define L 512
#define H2 (2*H)

// ---------------- device scratch (static: no runtime allocation) -------------
__device__ float g_attn_logits[L];
__device__ float g_attn_applied[H];
__device__ float g_x[H];          // relu(combine) = GRU input
__device__ float g_hnew[H];
__device__ float g_logits[V];

// ---------------- helpers ----------------------------------------------------
__device__ __forceinline__ float warp_sum(float v) {
    #pragma unroll
    for (int o = 16; o > 0; o >>= 1) v += __shfl_down_sync(0xffffffffu, v, o);
    return v;
}

__device__ __forceinline__ float warp_max(float v) {
    #pragma unroll
    for (int o = 16; o > 0; o >>= 1) v = fmaxf(v, __shfl_down_sync(0xffffffffu, v, o));
    return v;
}

__device__ __forceinline__ float sigmoidf_(float x) {
    return 1.0f / (1.0f + expf(-x));
}

// 1) attn logits: one block per l; dot(cat(emb_row,h), attn_W[l]) + attn_b[l]
//    float4 loads: each thread handles 2 float4 of the 512-float4 row.
__global__ void k_attn_logits(const int* __restrict__ idx,
                              const float* __restrict__ hidden,
                              const float* __restrict__ emb,
                              const float* __restrict__ attn_W,
                              const float* __restrict__ attn_b) {
    const int l = blockIdx.x;
    const float4* __restrict__ e4 = (const float4*)(emb + (size_t)idx[0] * H);
    const float4* __restrict__ h4 = (const float4*)hidden;
    const float4* __restrict__ w4 = (const float4*)(attn_W + (size_t)l * H2);
    float s = 0.f;
    #pragma unroll
    for (int i = 0; i < 2; ++i) {        // 512 float4 / 256 threads = 2
        const int c = threadIdx.x + i * 256;   // [0,512)
        const float4 w = w4[c];
        const float4 v = (c < 256) ? e4[c] : h4[c - 256];
        s += w.x * v.x + w.y * v.y + w.z * v.z + w.w * v.w;
    }
    __shared__ float sh[8];
    s = warp_sum(s);
    const int lane = threadIdx.x & 31, wid = threadIdx.x >> 5;
    if (lane == 0) sh[wid] = s;
    __syncthreads();
    if (wid == 0) {
        s = (lane < 8) ? sh[lane] : 0.f;
        s = warp_sum(s);
        if (lane == 0) g_attn_logits[l] = s + attn_b[l];
    }
}

// 2) fused softmax(L) + attn_applied.
//    Each block (256 thr) redundantly computes the softmax over the 512
//    logits in smem, then computes its 256 h-slice of attn_applied.
//    Block 0 additionally writes attn_weights to d_out[V+H .. V+H+L).
__global__ void k_softmax_attn_applied(const float* __restrict__ enc,
                                       float* __restrict__ out) {
    __shared__ float wsh[L];
    const int t = threadIdx.x;          // 0..255

    // load logits (2 per thread)
    float v0 = g_attn_logits[t];
    float v1 = g_attn_logits[t + 256];

    // block max over 512 values
    __shared__ float red[8];
    float m = fmaxf(v0, v1);
    m = warp_max(m);
    const int lane = t & 31, wid = t >> 5;
    if (lane == 0) red[wid] = m;
    __syncthreads();
    if (t < 8) {
        float x = red[t];
        #pragma unroll
        for (int o = 4; o > 0; o >>= 1) x = fmaxf(x, __shfl_down_sync(0xffu, x, o));
        if (t == 0) red[0] = x;
    }
    __syncthreads();
    const float mx = red[0];
    __syncthreads();

    // exp + block sum
    const float e0 = expf(v0 - mx);
    const float e1 = expf(v1 - mx);
    float s = e0 + e1;
    s = warp_sum(s);
    if (lane == 0) red[wid] = s;
    __syncthreads();
    if (t < 8) {
        float x = red[t];
        #pragma unroll
        for (int o = 4; o > 0; o >>= 1) x += __shfl_down_sync(0xffu, x, o);
        if (t == 0) red[0] = x;
    }
    __syncthreads();
    const float inv = 1.0f / red[0];
    wsh[t]       = e0 * inv;
    wsh[t + 256] = e1 * inv;
    __syncthreads();

    if (blockIdx.x == 0) {
        out[V + H + t]       = wsh[t];
        out[V + H + t + 256] = wsh[t + 256];
    }

    // attn_applied for this block's h-slice
    const int h = blockIdx.x * blockDim.x + t;
    if (h < H) {
        float acc = 0.f;
        #pragma unroll 8
        for (int l = 0; l < L; ++l) acc += wsh[l] * enc[(size_t)l * H + h];
        g_attn_applied[h] = acc;
    }
}

// 3) x = relu(comb_W @ [emb_row; attn_applied] + comb_b); one warp per row
__global__ void k_combine(const int* __restrict__ idx,
                          const float* __restrict__ emb,
                          const float* __restrict__ comb_W,
                          const float* __restrict__ comb_b) {
    const int lane = threadIdx.x & 31;
    const int row = (blockIdx.x * blockDim.x + threadIdx.x) >> 5;
    if (row >= H) return;
    const float4* __restrict__ w4 =
        (const float4*)(comb_W + (size_t)row * H2);
    const float4* __restrict__ e4 =
        (const float4*)(emb + (size_t)idx[0] * H);
    const float4* __restrict__ a4 = (const float4*)g_attn_applied;
    float s = 0.f;
    #pragma unroll
    for (int i = 0; i < 16; ++i) {   // 2048 floats / 4 / 32 lanes = 16
        const int c = lane + i * 32; // float4 index in [0,512)
        float4 w = w4[c];
        float4 v = (c < 256) ? e4[c] : a4[c - 256];
        s += w.x * v.x + w.y * v.y + w.z * v.z + w.w * v.w;
    }
    s = warp_sum(s);
    if (lane == 0) g_x[row] = fmaxf(s + comb_b[row], 0.f);
}

// 4) fused GRU step; one warp per h, 6 dot products of length H.
//    Writes g_hnew and d_out[V .. V+H)
__global__ void k_gru(const float* __restrict__ hidden,
                      const float* __restrict__ W_ih,
                      const float* __restrict__ W_hh,
                      const float* __restrict__ b_ih,
                      const float* __restrict__ b_hh,
                      float* __restrict__ out) {
    const int lane = threadIdx.x & 31;
    const int h = (blockIdx.x * blockDim.x + threadIdx.x) >> 5;
    if (h >= H) return;
    const float4* __restrict__ x4 = (const float4*)g_x;
    const float4* __restrict__ h4 = (const float4*)hidden;
    const float4* __restrict__ wir = (const float4*)(W_ih + (size_t)h * H);
    const float4* __restrict__ wiz = (const float4*)(W_ih + (size_t)(H + h) * H);
    const float4* __restrict__ win = (const float4*)(W_ih + (size_t)(2 * H + h) * H);
    const float4* __restrict__ whr = (const float4*)(W_hh + (size_t)h * H);
    const float4* __restrict__ whz = (const float4*)(W_hh + (size_t)(H + h) * H);
    const float4* __restrict__ whn = (const float4*)(W_hh + (size_t)(2 * H + h) * H);
    float sir = 0.f, siz = 0.f, sin_ = 0.f, shr = 0.f, shz = 0.f, shn = 0.f;
    #pragma unroll
    for (int i = 0; i < 8; ++i) {    // 1024/4/32 = 8 float4 per lane
        const int c = lane + i * 32;
        float4 xv = x4[c], hv = h4[c];
        float4 a;
        a = wir[c]; sir  += a.x*xv.x + a.y*xv.y + a.z*xv.z + a.w*xv.w;
        a = wiz[c]; siz  += a.x*xv.x + a.y*xv.y + a.z*xv.z + a.w*xv.w;
        a = win[c]; sin_ += a.x*xv.x + a.y*xv.y + a.z*xv.z + a.w*xv.w;
        a = whr[c]; shr  += a.x*hv.x + a.y*hv.y + a.z*hv.z + a.w*hv.w;
        a = whz[c]; shz  += a.x*hv.x + a.y*hv.y + a.z*hv.z + a.w*hv.w;
        a = whn[c]; shn  += a.x*hv.x + a.y*hv.y + a.z*hv.z + a.w*hv.w;
    }
    sir = warp_sum(sir); siz = warp_sum(siz); sin_ = warp_sum(sin_);
    shr = warp_sum(shr); shz = warp_sum(shz); shn = warp_sum(shn);
    if (lane == 0) {
        const float gi_r = sir + b_ih[h];
        const float gi_z = siz + b_ih[H + h];
        const float gi_n = sin_ + b_ih[2 * H + h];
        const float gh_r = shr + b_hh[h];
        const float gh_z = shz + b_hh[H + h];
        const float gh_n = shn + b_hh[2 * H + h];
        const float r = sigmoidf_(gi_r + gh_r);
        const float z = sigmoidf_(gi_z + gh_z);
        const float n = tanhf(gi_n + r * gh_n);
        const float hn = (1.0f - z) * n + z * hidden[h];
        g_hnew[h] = hn;
        out[V + h] = hn;
    }
}

// 5) vocab GEMV: logits[v] = dot(h_new, out_W[v]) + out_b[v].
//    FOUR rows per warp: 32 independent LDG.128 in flight per lane before the
//    reduction (under M_max~55), maximizing per-warp MLP. h_new staged in
//    shared. This is the 206 MB / roofline kernel.
__global__ void k_vocab_gemv(const float* __restrict__ out_W,
                             const float* __restrict__ out_b) {
    __shared__ float4 hn4[H / 4];
    for (int i = threadIdx.x; i < H / 4; i += blockDim.x)
        hn4[i] = ((const float4*)g_hnew)[i];
    __syncthreads();
    const int lane = threadIdx.x & 31;
    const int warp = (blockIdx.x * blockDim.x + threadIdx.x) >> 5;
    const int row0 = warp * 4;
    if (row0 >= V) return;
    const bool h1 = (row0 + 1) < V;
    const bool h2 = (row0 + 2) < V;
    const bool h3 = (row0 + 3) < V;
    const float4* __restrict__ w0 = (const float4*)(out_W + (size_t)row0 * H);
    const float4* __restrict__ w1 = (const float4*)(out_W + (size_t)(row0 + 1) * H);
    const float4* __restrict__ w2 = (const float4*)(out_W + (size_t)(row0 + 2) * H);
    const float4* __restrict__ w3 = (const float4*)(out_W + (size_t)(row0 + 3) * H);
    float s0 = 0.f, s1 = 0.f, s2 = 0.f, s3 = 0.f;
    #pragma unroll
    for (int i = 0; i < 8; ++i) {
        const int c = lane + i * 32;
        const float4 v = hn4[c];
        float4 a;
        a = w0[c];        s0 += a.x*v.x + a.y*v.y + a.z*v.z + a.w*v.w;
        if (h1) { a = w1[c]; s1 += a.x*v.x + a.y*v.y + a.z*v.z + a.w*v.w; }
        if (h2) { a = w2[c]; s2 += a.x*v.x + a.y*v.y + a.z*v.z + a.w*v.w; }
        if (h3) { a = w3[c]; s3 += a.x*v.x + a.y*v.y + a.z*v.z + a.w*v.w; }
    }
    s0 = warp_sum(s0);
    s1 = warp_sum(s1);
    s2 = warp_sum(s2);
    s3 = warp_sum(s3);
    if (lane == 0) {
        g_logits[row0] = s0 + out_b[row0];
        if (h1) g_logits[row0 + 1] = s1 + out_b[row0 + 1];
        if (h2) g_logits[row0 + 2] = s2 + out_b[row0 + 2];
        if (h3) g_logits[row0 + 3] = s3 + out_b[row0 + 3];
    }
}

// 6) fused log-sum-exp + final write.
//    Each of 16 blocks (1024 thr) redundantly reduces max and sum(exp) over
//    the V logits (L2-resident, ~201 KB; 16x redundant read = 3.2 MB L2
//    traffic, negligible), then writes its own 1/16 slice of the output.
__global__ void k_lse_write(float* __restrict__ out) {
    __shared__ float sh[1024];
    const int t = threadIdx.x;
    const float4* __restrict__ l4 = (const float4*)g_logits;
    const int n4 = V / 4;                 // 12564

    // --- max over V ---
    float m = -INFINITY;
    for (int i = t; i < n4; i += 1024) {
        float4 v = l4[i];
        m = fmaxf(m, fmaxf(fmaxf(v.x, v.y), fmaxf(v.z, v.w)));
    }
    if (t == 0) {
        for (int v = n4 * 4; v < V; ++v) m = fmaxf(m, g_logits[v]);
    }
    sh[t] = m;
    __syncthreads();
    for (int s = 512; s > 0; s >>= 1) {
        if (t < s) sh[t] = fmaxf(sh[t], sh[t + s]);
        __syncthreads();
    }
    const float mx = sh[0];
    __syncthreads();

    // --- sum exp ---
    float sum = 0.f;
    for (int i = t; i < n4; i += 1024) {
        float4 v = l4[i];
        sum += expf(v.x - mx) + expf(v.y - mx) + expf(v.z - mx) + expf(v.w - mx);
    }
    if (t == 0) {
        for (int v = n4 * 4; v < V; ++v) sum += expf(g_logits[v] - mx);
    }
    sh[t] = sum;
    __syncthreads();
    for (int s = 512; s > 0; s >>= 1) {
        if (t < s) sh[t] += sh[t + s];
        __syncthreads();
    }
    const float c = mx + logf(sh[0]);
    __syncthreads();

    // --- write this block's slice (float4 granularity + tail on last block) ---
    const int per_block = (n4 + gridDim.x - 1) / gridDim.x;
    const int i0 = blockIdx.x * per_block;
    const int i1 = min(i0 + per_block, n4);
    for (int i = i0 + t; i < i1; i += 1024) {
        float4 v = l4[i];
        float4 r;
        r.x = v.x - c; r.y = v.y - c; r.z = v.z - c; r.w = v.w - c;
        ((float4*)out)[i] = r;
    }
    if (blockIdx.x == gridDim.x - 1 && t == 0) {
        for (int v = n4 * 4; v < V; ++v) out[v] = g_logits[v] - c;
    }
}

// ---------------- launcher ----------------------------------------------------
extern "C" void kernel_launch(void* const* d_in, const int* in_sizes, int n_in,
                              void* d_out, int out_size) {
    const int*   idx     = (const int*)  d_in[0];
    const float* hidden  = (const float*)d_in[1];
    const float* enc     = (const float*)d_in[2];
    const float* emb     = (const float*)d_in[3];
    const float* attn_W  = (const float*)d_in[4];
    const float* attn_b  = (const float*)d_in[5];
    const float* comb_W  = (const float*)d_in[6];
    const float* comb_b  = (const float*)d_in[7];
    const float* W_ih    = (const float*)d_in[8];
    const float* W_hh    = (const float*)d_in[9];
    const float* b_ih    = (const float*)d_in[10];
    const float* b_hh    = (const float*)d_in[11];
    const float* out_W   = (const float*)d_in[12];
    const float* out_b   = (const float*)d_in[13];
    float* out = (float*)d_out;

    k_attn_logits<<<L, 256>>>(idx, hidden, emb, attn_W, attn_b);
    k_softmax_attn_applied<<<(H + 255) / 256, 256>>>(enc, out);
    k_combine<<<(H * 32 + 255) / 256, 256>>>(idx, emb, comb_W, comb_b);
    k_gru<<<(H * 32 + 255) / 256, 256>>>(hidden, W_ih, W_hh, b_ih, b_hh, out);
    {
        // 4 rows per warp, 16 warps (512 threads) per block
        const int rows_per_block = 64;
        const int blocks = (V + rows_per_block - 1) / rows_per_block;  // 786
        k_vocab_gemv<<<blocks, 512>>>(out_W, out_b);
    }
    k_lse_write<<<16, 1024>>>(out);
}

// round 9
// speedup vs baseline: 1.5319x; 1.5319x over previous
#include <cuda_runtime.h>
#include <math.h>

#define H 1024
#define V 50257
#define L 512
#define H2 (2*H)
#define H3 (3*H)

// ---------------- device scratch (static: no runtime allocation) -------------
__device__ float g_attn_logits[L];
__device__ float g_attn_applied[H];
__device__ float g_x[H];          // relu(combine) = GRU input
__device__ float g_gi[H3];        // x @ W_ih.T   (pre-bias)
__device__ float g_gh[H3];        // h @ W_hh.T   (pre-bias)
__device__ float g_hnew[H];
__device__ float g_logits[V];

// ---------------- helpers ----------------------------------------------------
__device__ __forceinline__ float warp_sum(float v) {
    #pragma unroll
    for (int o = 16; o > 0; o >>= 1) v += __shfl_down_sync(0xffffffffu, v, o);
    return v;
}

__device__ __forceinline__ float warp_max(float v) {
    #pragma unroll
    for (int o = 16; o > 0; o >>= 1) v = fmaxf(v, __shfl_down_sync(0xffffffffu, v, o));
    return v;
}

__device__ __forceinline__ float sigmoidf_(float x) {
    return 1.0f / (1.0f + expf(-x));
}

// 1) attn logits: one block per l; dot(cat(emb_row,h), attn_W[l]) + attn_b[l].
//    Blocks 0..3 also zero g_attn_applied for the atomic accumulation in (2).
__global__ void k_attn_logits(const int* __restrict__ idx,
                              const float* __restrict__ hidden,
                              const float* __restrict__ emb,
                              const float* __restrict__ attn_W,
                              const float* __restrict__ attn_b) {
    const int l = blockIdx.x;
    if (l < 4) g_attn_applied[l * 256 + threadIdx.x] = 0.f;
    const float4* __restrict__ e4 = (const float4*)(emb + (size_t)idx[0] * H);
    const float4* __restrict__ h4 = (const float4*)hidden;
    const float4* __restrict__ w4 = (const float4*)(attn_W + (size_t)l * H2);
    float s = 0.f;
    #pragma unroll
    for (int i = 0; i < 2; ++i) {        // 512 float4 / 256 threads = 2
        const int c = threadIdx.x + i * 256;   // [0,512)
        const float4 w = w4[c];
        const float4 v = (c < 256) ? e4[c] : h4[c - 256];
        s += w.x * v.x + w.y * v.y + w.z * v.z + w.w * v.w;
    }
    __shared__ float sh[8];
    s = warp_sum(s);
    const int lane = threadIdx.x & 31, wid = threadIdx.x >> 5;
    if (lane == 0) sh[wid] = s;
    __syncthreads();
    if (wid == 0) {
        s = (lane < 8) ? sh[lane] : 0.f;
        s = warp_sum(s);
        if (lane == 0) g_attn_logits[l] = s + attn_b[l];
    }
}

// 2) fused softmax(L) + attn_applied, L-split for parallelism.
//    Grid (4 h-blocks, 8 l-chunks) = 32 CTAs. Each block redundantly computes
//    the 512-wide softmax in smem (trivial), then accumulates its 64-l chunk
//    into g_attn_applied via atomicAdd (zeroed in kernel 1).
//    Block (0,0) writes attn_weights to d_out[V+H .. V+H+L).
__global__ void k_softmax_attn_applied(const float* __restrict__ enc,
                                       float* __restrict__ out) {
    __shared__ float wsh[L];
    const int t = threadIdx.x;          // 0..255

    // load logits (2 per thread)
    float v0 = g_attn_logits[t];
    float v1 = g_attn_logits[t + 256];

    // block max over 512 values
    __shared__ float red[8];
    float m = fmaxf(v0, v1);
    m = warp_max(m);
    const int lane = t & 31, wid = t >> 5;
    if (lane == 0) red[wid] = m;
    __syncthreads();
    if (t < 8) {
        float x = red[t];
        #pragma unroll
        for (int o = 4; o > 0; o >>= 1) x = fmaxf(x, __shfl_down_sync(0xffu, x, o));
        if (t == 0) red[0] = x;
    }
    __syncthreads();
    const float mx = red[0];
    __syncthreads();

    // exp + block sum
    const float e0 = expf(v0 - mx);
    const float e1 = expf(v1 - mx);
    float s = e0 + e1;
    s = warp_sum(s);
    if (lane == 0) red[wid] = s;
    __syncthreads();
    if (t < 8) {
        float x = red[t];
        #pragma unroll
        for (int o = 4; o > 0; o >>= 1) x += __shfl_down_sync(0xffu, x, o);
        if (t == 0) red[0] = x;
    }
    __syncthreads();
    const float inv = 1.0f / red[0];
    wsh[t]       = e0 * inv;
    wsh[t + 256] = e1 * inv;
    __syncthreads();

    if (blockIdx.x == 0 && blockIdx.y == 0) {
        out[V + H + t]       = wsh[t];
        out[V + H + t + 256] = wsh[t + 256];
    }

    // accumulate this l-chunk into attn_applied for this block's h-slice
    const int h = blockIdx.x * blockDim.x + t;
    const int l0 = blockIdx.y * (L / 8);      // 64 l per chunk
    float acc = 0.f;
    #pragma unroll 8
    for (int li = 0; li < L / 8; ++li) {
        const int l = l0 + li;
        acc += wsh[l] * enc[(size_t)l * H + h];
    }
    atomicAdd(&g_attn_applied[h], acc);
}

// 3) x = relu(comb_W @ [emb_row; attn_applied] + comb_b); one warp per row.
//    128-thread CTAs -> 256 CTAs for full SM coverage.
__global__ void k_combine(const int* __restrict__ idx,
                          const float* __restrict__ emb,
                          const float* __restrict__ comb_W,
                          const float* __restrict__ comb_b) {
    const int lane = threadIdx.x & 31;
    const int row = (blockIdx.x * blockDim.x + threadIdx.x) >> 5;
    if (row >= H) return;
    const float4* __restrict__ w4 =
        (const float4*)(comb_W + (size_t)row * H2);
    const float4* __restrict__ e4 =
        (const float4*)(emb + (size_t)idx[0] * H);
    const float4* __restrict__ a4 = (const float4*)g_attn_applied;
    float s = 0.f;
    #pragma unroll
    for (int i = 0; i < 16; ++i) {   // 2048 floats / 4 / 32 lanes = 16
        const int c = lane + i * 32; // float4 index in [0,512)
        float4 w = w4[c];
        float4 v = (c < 256) ? e4[c] : a4[c - 256];
        s += w.x * v.x + w.y * v.y + w.z * v.z + w.w * v.w;
    }
    s = warp_sum(s);
    if (lane == 0) g_x[row] = fmaxf(s + comb_b[row], 0.f);
}

// 4a) GRU GEMV: one warp per row of the stacked [W_ih; W_hh] (6144 rows).
//     1536 CTAs of 128 threads -> ~10 CTAs/SM, 6x the warps of the old fused
//     version (which measured occ=10.6%, DRAM=20.8%).
__global__ void k_gru_gemv(const float* __restrict__ hidden,
                           const float* __restrict__ W_ih,
                           const float* __restrict__ W_hh) {
    const int lane = threadIdx.x & 31;
    const int w = (blockIdx.x * blockDim.x + threadIdx.x) >> 5;  // 0..6143
    if (w >= 2 * H3) return;
    const float4* __restrict__ wrow;
    const float4* __restrict__ vec;
    float* dst;
    if (w < H3) {
        wrow = (const float4*)(W_ih + (size_t)w * H);
        vec  = (const float4*)g_x;
        dst  = &g_gi[w];
    } else {
        const int r = w - H3;
        wrow = (const float4*)(W_hh + (size_t)r * H);
        vec  = (const float4*)hidden;
        dst  = &g_gh[r];
    }
    float s = 0.f;
    #pragma unroll
    for (int i = 0; i < 8; ++i) {    // 1024/4/32 = 8 float4 per lane
        const int c = lane + i * 32;
        const float4 a = wrow[c];
        const float4 v = vec[c];
        s += a.x * v.x + a.y * v.y + a.z * v.z + a.w * v.w;
    }
    s = warp_sum(s);
    if (lane == 0) *dst = s;
}

// 4b) GRU gates: elementwise, 4 h per thread with float4 loads.
//     Writes g_hnew (float4, aligned) and d_out[V .. V+H) with SCALAR stores
//     (out + V is NOT 16B-aligned since V=50257 is odd -> float4 store traps).
__global__ void k_gru_gates(const float* __restrict__ hidden,
                            const float* __restrict__ b_ih,
                            const float* __restrict__ b_hh,
                            float* __restrict__ out) {
    const int q = blockIdx.x * blockDim.x + threadIdx.x;  // float4 index [0,256)
    if (q >= H / 4) return;
    const float4 gir = ((const float4*)g_gi)[q];
    const float4 giz = ((const float4*)(g_gi + H))[q];
    const float4 gin = ((const float4*)(g_gi + 2 * H))[q];
    const float4 ghr = ((const float4*)g_gh)[q];
    const float4 ghz = ((const float4*)(g_gh + H))[q];
    const float4 ghn = ((const float4*)(g_gh + 2 * H))[q];
    const float4 bir = ((const float4*)b_ih)[q];
    const float4 biz = ((const float4*)(b_ih + H))[q];
    const float4 bin = ((const float4*)(b_ih + 2 * H))[q];
    const float4 bhr = ((const float4*)b_hh)[q];
    const float4 bhz = ((const float4*)(b_hh + H))[q];
    const float4 bhn = ((const float4*)(b_hh + 2 * H))[q];
    const float4 hv  = ((const float4*)hidden)[q];
    float4 hn;
    {
        const float r = sigmoidf_((gir.x + bir.x) + (ghr.x + bhr.x));
        const float z = sigmoidf_((giz.x + biz.x) + (ghz.x + bhz.x));
        const float n = tanhf((gin.x + bin.x) + r * (ghn.x + bhn.x));
        hn.x = (1.0f - z) * n + z * hv.x;
    }
    {
        const float r = sigmoidf_((gir.y + bir.y) + (ghr.y + bhr.y));
        const float z = sigmoidf_((giz.y + biz.y) + (ghz.y + bhz.y));
        const float n = tanhf((gin.y + bin.y) + r * (ghn.y + bhn.y));
        hn.y = (1.0f - z) * n + z * hv.y;
    }
    {
        const float r = sigmoidf_((gir.z + bir.z) + (ghr.z + bhr.z));
        const float z = sigmoidf_((giz.z + biz.z) + (ghz.z + bhz.z));
        const float n = tanhf((gin.z + bin.z) + r * (ghn.z + bhn.z));
        hn.z = (1.0f - z) * n + z * hv.z;
    }
    {
        const float r = sigmoidf_((gir.w + bir.w) + (ghr.w + bhr.w));
        const float z = sigmoidf_((giz.w + biz.w) + (ghz.w + bhz.w));
        const float n = tanhf((gin.w + bin.w) + r * (ghn.w + bhn.w));
        hn.w = (1.0f - z) * n + z * hv.w;
    }
    ((float4*)g_hnew)[q] = hn;                 // g_hnew is 16B-aligned: OK
    float* o = out + V + q * 4;                // misaligned base -> scalar stores
    o[0] = hn.x; o[1] = hn.y; o[2] = hn.z; o[3] = hn.w;
}

// 5) vocab GEMV: logits[v] = dot(h_new, out_W[v]) + out_b[v].
//    FOUR rows per warp (32 independent LDG.128/lane in flight, under
//    M_max~55); 256-thread CTAs so multiple CTAs fit per SM. Branch-free
//    tail via row clamping. This is the 206 MB / roofline kernel.
__global__ void __launch_bounds__(256)
k_vocab_gemv(const float* __restrict__ out_W,
             const float* __restrict__ out_b) {
    __shared__ float4 hn4[H / 4];
    for (int i = threadIdx.x; i < H / 4; i += blockDim.x)
        hn4[i] = ((const float4*)g_hnew)[i];
    __syncthreads();
    const int lane = threadIdx.x & 31;
    const int warp = (blockIdx.x * blockDim.x + threadIdx.x) >> 5;
    const int row0 = warp * 4;
    if (row0 >= V) return;
    const int r1 = min(row0 + 1, V - 1);
    const int r2 = min(row0 + 2, V - 1);
    const int r3 = min(row0 + 3, V - 1);
    const float4* __restrict__ w0 = (const float4*)(out_W + (size_t)row0 * H);
    const float4* __restrict__ w1 = (const float4*)(out_W + (size_t)r1 * H);
    const float4* __restrict__ w2 = (const float4*)(out_W + (size_t)r2 * H);
    const float4* __restrict__ w3 = (const float4*)(out_W + (size_t)r3 * H);
    float s0 = 0.f, s1 = 0.f, s2 = 0.f, s3 = 0.f;
    #pragma unroll
    for (int i = 0; i < 8; ++i) {
        const int c = lane + i * 32;
        const float4 v = hn4[c];
        float4 a;
        a = w0[c]; s0 += a.x*v.x + a.y*v.y + a.z*v.z + a.w*v.w;
        a = w1[c]; s1 += a.x*v.x + a.y*v.y + a.z*v.z + a.w*v.w;
        a = w2[c]; s2 += a.x*v.x + a.y*v.y + a.z*v.z + a.w*v.w;
        a = w3[c]; s3 += a.x*v.x + a.y*v.y + a.z*v.z + a.w*v.w;
    }
    s0 = warp_sum(s0);
    s1 = warp_sum(s1);
    s2 = warp_sum(s2);
    s3 = warp_sum(s3);
    if (lane == 0) {
        g_logits[row0] = s0 + out_b[row0];
        if (row0 + 1 < V) g_logits[row0 + 1] = s1 + out_b[r1];
        if (row0 + 2 < V) g_logits[row0 + 2] = s2 + out_b[r2];
        if (row0 + 3 < V) g_logits[row0 + 3] = s3 + out_b[r3];
    }
}

// 6) fused log-sum-exp + final write.
//    Each of 26 blocks (1024 thr) redundantly reduces max and sum(exp) over
//    the V logits (L2-resident ~201 KB), then writes its own slice.
__global__ void k_lse_write(float* __restrict__ out) {
    __shared__ float sh[1024];
    const int t = threadIdx.x;
    const float4* __restrict__ l4 = (const float4*)g_logits;
    const int n4 = V / 4;                 // 12564

    // --- max over V ---
    float m = -INFINITY;
    for (int i = t; i < n4; i += 1024) {
        float4 v = l4[i];
        m = fmaxf(m, fmaxf(fmaxf(v.x, v.y), fmaxf(v.z, v.w)));
    }
    if (t == 0) {
        for (int v = n4 * 4; v < V; ++v) m = fmaxf(m, g_logits[v]);
    }
    sh[t] = m;
    __syncthreads();
    for (int s = 512; s > 0; s >>= 1) {
        if (t < s) sh[t] = fmaxf(sh[t], sh[t + s]);
        __syncthreads();
    }
    const float mx = sh[0];
    __syncthreads();

    // --- sum exp ---
    float sum = 0.f;
    for (int i = t; i < n4; i += 1024) {
        float4 v = l4[i];
        sum += expf(v.x - mx) + expf(v.y - mx) + expf(v.z - mx) + expf(v.w - mx);
    }
    if (t == 0) {
        for (int v = n4 * 4; v < V; ++v) sum += expf(g_logits[v] - mx);
    }
    sh[t] = sum;
    __syncthreads();
    for (int s = 512; s > 0; s >>= 1) {
        if (t < s) sh[t] += sh[t + s];
        __syncthreads();
    }
    const float c = mx + logf(sh[0]);
    __syncthreads();

    // --- write this block's slice (float4 granularity + tail on last block) ---
    const int per_block = (n4 + gridDim.x - 1) / gridDim.x;
    const int i0 = blockIdx.x * per_block;
    const int i1 = min(i0 + per_block, n4);
    for (int i = i0 + t; i < i1; i += 1024) {
        float4 v = l4[i];
        float4 r;
        r.x = v.x - c; r.y = v.y - c; r.z = v.z - c; r.w = v.w - c;
        ((float4*)out)[i] = r;
    }
    if (blockIdx.x == gridDim.x - 1 && t == 0) {
        for (int v = n4 * 4; v < V; ++v) out[v] = g_logits[v] - c;
    }
}

// ---------------- launcher ----------------------------------------------------
extern "C" void kernel_launch(void* const* d_in, const int* in_sizes, int n_in,
                              void* d_out, int out_size) {
    const int*   idx     = (const int*)  d_in[0];
    const float* hidden  = (const float*)d_in[1];
    const float* enc     = (const float*)d_in[2];
    const float* emb     = (const float*)d_in[3];
    const float* attn_W  = (const float*)d_in[4];
    const float* attn_b  = (const float*)d_in[5];
    const float* comb_W  = (const float*)d_in[6];
    const float* comb_b  = (const float*)d_in[7];
    const float* W_ih    = (const float*)d_in[8];
    const float* W_hh    = (const float*)d_in[9];
    const float* b_ih    = (const float*)d_in[10];
    const float* b_hh    = (const float*)d_in[11];
    const float* out_W   = (const float*)d_in[12];
    const float* out_b   = (const float*)d_in[13];
    float* out = (float*)d_out;

    k_attn_logits<<<L, 256>>>(idx, hidden, emb, attn_W, attn_b);
    {
        dim3 grid(H / 256, 8);           // 4 h-blocks x 8 l-chunks = 32 CTAs
        k_softmax_attn_applied<<<grid, 256>>>(enc, out);
    }
    k_combine<<<(H * 32 + 127) / 128, 128>>>(idx, emb, comb_W, comb_b);
    k_gru_gemv<<<(2 * H3 * 32 + 127) / 128, 128>>>(hidden, W_ih, W_hh);
    k_gru_gates<<<1, 256>>>(hidden, b_ih, b_hh, out);
    {
        // 4 rows per warp, 8 warps (256 threads) per block
        const int rows_per_block = 32;
        const int blocks = (V + rows_per_block - 1) / rows_per_block;  // 1571
        k_vocab_gemv<<<blocks, 256>>>(out_W, out_b);
    }
    k_lse_write<<<26, 1024>>>(out);
}